// round 6
// baseline (speedup 1.0000x reference)
#include <cuda_runtime.h>
#include <math.h>

// LSTM: T=512 steps, B=128 batch, D_in=512, H=512.
// Strategy:
//   1. prep_kernel: repack weights into gate-interleaved layout col = j*4 + gate
//      (Wx = rows [0,512) of each gate weight, Wh = rows [512,1024)), build bias,
//      zero the c-state scratch (re-zeroed every replay for determinism).
//   2. sgemm_x: Gx[65536 x 2048] = X[65536 x 512] @ Wx + bias  (parallel, fp32 SGEMM)
//   3. 512x lstm_step: gates = Gx[t] + h_{t-1} @ Wh, fused LSTM epilogue,
//      h_t written straight into the output tensor slice for step t.
//   4. finalize: copy h_511 -> hx region, c -> cx region.

#define T_STEPS 512
#define BATCH   128
#define HID     512
#define DIN     512
#define NG      2048                       // 4 * HID, gate-interleaved
#define M_ALL   (T_STEPS * BATCH)          // 65536

// Scratch (no dynamic allocation allowed): 512MB Gx + weights + states.
__device__ float g_Gx[(size_t)M_ALL * NG];     // 512 MB
__device__ float g_Wx[DIN * NG];               // 4 MB
__device__ float g_Wh[HID * NG];               // 4 MB
__device__ float g_bias[NG];
__device__ float g_c[BATCH * HID];             // cell state, zeroed by prep each launch
__device__ float g_zero[BATCH * HID];          // zero-initialized, never written (h_{-1})

// ---------------------------------------------------------------------------
// Weight repack + c-state zero. Runs every launch (deterministic).
// g_Wx[k][j*4+g] = W_g[k][j];  g_Wh[k][j*4+g] = W_g[512+k][j];  g_bias[j*4+g]=b_g[j]
// ---------------------------------------------------------------------------
__global__ __launch_bounds__(256) void prep_kernel(
    const float* __restrict__ Wf, const float* __restrict__ bf,
    const float* __restrict__ Wi, const float* __restrict__ bi,
    const float* __restrict__ Wg, const float* __restrict__ bg,
    const float* __restrict__ Wo, const float* __restrict__ bo)
{
    int idx = blockIdx.x * 256 + threadIdx.x;
    if (idx < DIN * NG) {
        int k   = idx / NG;
        int col = idx % NG;
        int j   = col >> 2;
        int g   = col & 3;
        const float* W = (g == 0) ? Wf : (g == 1) ? Wi : (g == 2) ? Wg : Wo;
        g_Wx[idx] = W[(size_t)k * HID + j];
        g_Wh[idx] = W[(size_t)(DIN + k) * HID + j];
        if (k == 0) {
            const float* b = (g == 0) ? bf : (g == 1) ? bi : (g == 2) ? bg : bo;
            g_bias[col] = b[j];
        }
    }
    if (idx < BATCH * HID) g_c[idx] = 0.0f;
}

// ---------------------------------------------------------------------------
// Phase 1: Gx = X @ Wx + bias.  M=65536, K=512, N=2048, fp32.
// 128x128 CTA tile, BK=16, 256 threads, 8x8 register microtile.
// ---------------------------------------------------------------------------
#define BM 128
#define BN 128
#define BK 16

__global__ __launch_bounds__(256) void sgemm_x(const float* __restrict__ A)
{
    __shared__ float As[BK][BM + 4];   // transposed A tile: As[k][m]; +4 keeps 16B align (528B rows)
    __shared__ float Bs[BK][BN];

    const int tid  = threadIdx.x;
    const int tx   = tid & 15;         // 0..15 -> 8 cols each
    const int ty   = tid >> 4;         // 0..15 -> 8 rows each
    const int row0 = blockIdx.y * BM;
    const int col0 = blockIdx.x * BN;

    float acc[8][8] = {};

    for (int k0 = 0; k0 < DIN; k0 += BK) {
        // Load A tile: 128 rows x 16 k  (512 float4, 2 per thread), store transposed.
        #pragma unroll
        for (int i = 0; i < 2; i++) {
            int idx = tid + i * 256;
            int ar  = idx >> 2;            // 0..127
            int ak  = (idx & 3) << 2;      // 0,4,8,12
            float4 v = *(const float4*)(A + (size_t)(row0 + ar) * DIN + k0 + ak);
            As[ak + 0][ar] = v.x;
            As[ak + 1][ar] = v.y;
            As[ak + 2][ar] = v.z;
            As[ak + 3][ar] = v.w;
        }
        // Load B tile: 16 k x 128 cols (512 float4, 2 per thread).
        #pragma unroll
        for (int i = 0; i < 2; i++) {
            int idx = tid + i * 256;
            int br  = idx >> 5;            // 0..15
            int bc  = (idx & 31) << 2;     // 0..124
            *(float4*)&Bs[br][bc] =
                *(const float4*)(g_Wx + (size_t)(k0 + br) * NG + col0 + bc);
        }
        __syncthreads();

        #pragma unroll
        for (int k = 0; k < BK; k++) {
            float a[8], b[8];
            *(float4*)(a)     = *(float4*)&As[k][ty * 8];
            *(float4*)(a + 4) = *(float4*)&As[k][ty * 8 + 4];
            *(float4*)(b)     = *(float4*)&Bs[k][tx * 8];
            *(float4*)(b + 4) = *(float4*)&Bs[k][tx * 8 + 4];
            #pragma unroll
            for (int i = 0; i < 8; i++)
                #pragma unroll
                for (int j = 0; j < 8; j++)
                    acc[i][j] += a[i] * b[j];
        }
        __syncthreads();
    }

    // Epilogue: + bias, store to g_Gx.
    #pragma unroll
    for (int i = 0; i < 8; i++) {
        int r = row0 + ty * 8 + i;
        #pragma unroll
        for (int j = 0; j < 8; j += 4) {
            int c = col0 + tx * 8 + j;
            float4 v;
            v.x = acc[i][j + 0] + g_bias[c + 0];
            v.y = acc[i][j + 1] + g_bias[c + 1];
            v.z = acc[i][j + 2] + g_bias[c + 2];
            v.w = acc[i][j + 3] + g_bias[c + 3];
            *(float4*)(g_Gx + (size_t)r * NG + c) = v;
        }
    }
}

// ---------------------------------------------------------------------------
// Phase 2, one step: gates[128 x 2048] = h_{t-1} @ Wh + Gx[t], fused epilogue.
// CTA tile 16 rows x 128 cols, BK=16, 256 threads, 2x4 microtile.
// Each thread's 4 columns are exactly (f,i,g,o) for one hidden unit j.
// Grid: (16, 8) = 128 CTAs.
// ---------------------------------------------------------------------------
__global__ __launch_bounds__(256) void lstm_step(int t, float* __restrict__ out)
{
    __shared__ float Hs[16][18];      // Hs[k][row], padded to avoid store conflicts
    __shared__ float Ws[16][128];

    const int tid  = threadIdx.x;
    const int tx   = tid & 31;        // 0..31 -> col group of 4 (= one hidden unit)
    const int ty   = tid >> 5;        // 0..7  -> 2 rows each
    const int col0 = blockIdx.x * 128;
    const int row0 = blockIdx.y * 16;

    const float* hprev = (t == 0) ? g_zero : (out + (size_t)(t - 1) * BATCH * HID);

    float acc[2][4] = {};

    for (int k0 = 0; k0 < HID; k0 += 16) {
        // h tile: 16 rows x 16 k -> 1 float/thread, stored transposed.
        {
            int hr = tid >> 4;         // 0..15
            int hk = tid & 15;         // 0..15
            Hs[hk][hr] = hprev[(size_t)(row0 + hr) * HID + k0 + hk];
        }
        // Wh tile: 16 k x 128 cols -> 2 float4/thread.
        #pragma unroll
        for (int i = 0; i < 2; i++) {
            int idx = tid + i * 256;
            int wr  = idx >> 5;
            int wc  = (idx & 31) << 2;
            *(float4*)&Ws[wr][wc] =
                *(const float4*)(g_Wh + (size_t)(k0 + wr) * NG + col0 + wc);
        }
        __syncthreads();

        #pragma unroll
        for (int k = 0; k < 16; k++) {
            float a0 = Hs[k][ty * 2 + 0];
            float a1 = Hs[k][ty * 2 + 1];
            float4 b = *(float4*)&Ws[k][tx * 4];
            acc[0][0] += a0 * b.x; acc[0][1] += a0 * b.y;
            acc[0][2] += a0 * b.z; acc[0][3] += a0 * b.w;
            acc[1][0] += a1 * b.x; acc[1][1] += a1 * b.y;
            acc[1][2] += a1 * b.z; acc[1][3] += a1 * b.w;
        }
        __syncthreads();
    }

    // Fused LSTM epilogue: this thread owns hidden unit j for 2 batch rows.
    const int j = (col0 >> 2) + tx;
    #pragma unroll
    for (int i = 0; i < 2; i++) {
        int row = row0 + ty * 2 + i;
        float4 gx = *(const float4*)(g_Gx + ((size_t)t * BATCH + row) * NG + col0 + tx * 4);
        float pf = acc[i][0] + gx.x;
        float pi = acc[i][1] + gx.y;
        float pg = acc[i][2] + gx.z;
        float po = acc[i][3] + gx.w;

        float f  = 1.0f / (1.0f + expf(-pf));
        float ig = 1.0f / (1.0f + expf(-pi));
        float g  = tanhf(pg);
        float o  = 1.0f / (1.0f + expf(-po));

        int   ci = row * HID + j;
        float cn = f * g_c[ci] + ig * g;
        g_c[ci]  = cn;
        out[(size_t)t * BATCH * HID + ci] = o * tanhf(cn);
    }
}

// ---------------------------------------------------------------------------
// Copy final h -> hx region, c -> cx region (output = [outputs, hx, cx]).
// ---------------------------------------------------------------------------
__global__ __launch_bounds__(256) void finalize(float* __restrict__ out)
{
    int idx = blockIdx.x * 256 + threadIdx.x;
    if (idx < BATCH * HID) {
        size_t base = (size_t)T_STEPS * BATCH * HID;
        out[base + idx]               = out[(size_t)(T_STEPS - 1) * BATCH * HID + idx];
        out[base + BATCH * HID + idx] = g_c[idx];
    }
}

// ---------------------------------------------------------------------------
extern "C" void kernel_launch(void* const* d_in, const int* in_sizes, int n_in,
                              void* d_out, int out_size)
{
    const float* x  = (const float*)d_in[0];
    const float* Wf = (const float*)d_in[1];
    const float* bf = (const float*)d_in[2];
    const float* Wi = (const float*)d_in[3];
    const float* bi = (const float*)d_in[4];
    const float* Wg = (const float*)d_in[5];
    const float* bg = (const float*)d_in[6];
    const float* Wo = (const float*)d_in[7];
    const float* bo = (const float*)d_in[8];
    float* out = (float*)d_out;

    // 1. repack weights + zero c state
    prep_kernel<<<(DIN * NG + 255) / 256, 256>>>(Wf, bf, Wi, bi, Wg, bg, Wo, bo);

    // 2. big input GEMM (parallel across all timesteps)
    dim3 g1(NG / BN, M_ALL / BM);
    sgemm_x<<<g1, 256>>>(x);

    // 3. sequential recurrence: one kernel per step
    dim3 gs(NG / 128, BATCH / 16);
    for (int t = 0; t < T_STEPS; t++)
        lstm_step<<<gs, 256>>>(t, out);

    // 4. final (hx, cx) — only if the output buffer includes them
    long long need = (long long)T_STEPS * BATCH * HID + 2LL * BATCH * HID;
    if ((long long)out_size >= need)
        finalize<<<(BATCH * HID + 255) / 256, 256>>>(out);
}

// round 7
// speedup vs baseline: 1.4087x; 1.4087x over previous
#include <cuda_runtime.h>
#include <math.h>

// LSTM T=512, B=128, D_in=H=512.
//  prep:        repack weights gate-interleaved (col = j*4 + gate), reset barrier.
//  sgemm_x:     Gx[65536 x 2048] = X @ Wx + bias   (FFMA2 fp32 SGEMM)
//  lstm_persist: ONE kernel, 128 co-resident CTAs, 512 steps with grid barrier.
//                Wh slice smem-resident, c-state register-resident, FFMA2 inner loop.

#define T_STEPS 512
#define BATCH   128
#define HID     512
#define DIN     512
#define NG      2048
#define M_ALL   (T_STEPS * BATCH)
#define BH      (BATCH * HID)          // 65536
#define NCTA    128

__device__ float g_Gx[(size_t)M_ALL * NG];     // 512 MB scratch
__device__ float g_Wx[DIN * NG];
__device__ float g_Wh[HID * NG];
__device__ float g_bias[NG];
__device__ unsigned int g_bar_count;
__device__ unsigned int g_bar_gen;

typedef unsigned long long ull;
union F4U { float4 f; ull u[2]; float s[4]; };

__device__ __forceinline__ void ffma2(ull& d, ull a, ull b) {
    asm("fma.rn.f32x2 %0, %1, %2, %0;" : "+l"(d) : "l"(a), "l"(b));
}
__device__ __forceinline__ ull dup2(float x) {
    ull r;
    asm("mov.b64 %0, {%1, %1};" : "=l"(r) : "f"(x));
    return r;
}
__device__ __forceinline__ void unpk(ull v, float& lo, float& hi) {
    asm("mov.b64 {%0, %1}, %2;" : "=f"(lo), "=f"(hi) : "l"(v));
}
__device__ __forceinline__ float sigm(float x) {
    return __fdividef(1.0f, 1.0f + __expf(-x));
}
__device__ __forceinline__ float tanh_(float x) {
    return __fdividef(2.0f, 1.0f + __expf(-2.0f * x)) - 1.0f;
}

// ---------------------------------------------------------------------------
__global__ __launch_bounds__(256) void prep_kernel(
    const float* __restrict__ Wf, const float* __restrict__ bf,
    const float* __restrict__ Wi, const float* __restrict__ bi,
    const float* __restrict__ Wg, const float* __restrict__ bg,
    const float* __restrict__ Wo, const float* __restrict__ bo)
{
    int idx = blockIdx.x * 256 + threadIdx.x;
    if (idx == 0) { g_bar_count = 0; g_bar_gen = 0; }
    if (idx < DIN * NG) {
        int k   = idx / NG;
        int col = idx % NG;
        int j   = col >> 2;
        int g   = col & 3;
        const float* W = (g == 0) ? Wf : (g == 1) ? Wi : (g == 2) ? Wg : Wo;
        g_Wx[idx] = W[(size_t)k * HID + j];
        g_Wh[idx] = W[(size_t)(DIN + k) * HID + j];
        if (k == 0) {
            const float* b = (g == 0) ? bf : (g == 1) ? bi : (g == 2) ? bg : bo;
            g_bias[col] = b[j];
        }
    }
}

// ---------------------------------------------------------------------------
// Phase 1: Gx = X @ Wx + bias.  128x128 tile, BK=16, 256 thr, 8x8 microtile, FFMA2.
// ---------------------------------------------------------------------------
#define BM 128
#define BN 128
#define BK 16

__global__ __launch_bounds__(256) void sgemm_x(const float* __restrict__ A)
{
    __shared__ float As[BK][BM + 4];   // [k][m]
    __shared__ float Bs[BK][BN];

    const int tid  = threadIdx.x;
    const int tx   = tid & 15;
    const int ty   = tid >> 4;
    const int row0 = blockIdx.y * BM;
    const int col0 = blockIdx.x * BN;

    ull acc[8][4];
    #pragma unroll
    for (int i = 0; i < 8; i++)
        #pragma unroll
        for (int jj = 0; jj < 4; jj++) acc[i][jj] = 0ull;

    for (int k0 = 0; k0 < DIN; k0 += BK) {
        #pragma unroll
        for (int i = 0; i < 2; i++) {
            int idx = tid + i * 256;
            int ar  = idx >> 2;
            int ak  = (idx & 3) << 2;
            float4 v = *(const float4*)(A + (size_t)(row0 + ar) * DIN + k0 + ak);
            As[ak + 0][ar] = v.x;
            As[ak + 1][ar] = v.y;
            As[ak + 2][ar] = v.z;
            As[ak + 3][ar] = v.w;
        }
        #pragma unroll
        for (int i = 0; i < 2; i++) {
            int idx = tid + i * 256;
            int br  = idx >> 5;
            int bc  = (idx & 31) << 2;
            *(float4*)&Bs[br][bc] =
                *(const float4*)(g_Wx + (size_t)(k0 + br) * NG + col0 + bc);
        }
        __syncthreads();

        #pragma unroll
        for (int k = 0; k < BK; k++) {
            F4U aA, aB, bA, bB;
            aA.f = *(float4*)&As[k][ty * 8];
            aB.f = *(float4*)&As[k][ty * 8 + 4];
            bA.f = *(float4*)&Bs[k][tx * 8];
            bB.f = *(float4*)&Bs[k][tx * 8 + 4];
            ull ad[8];
            #pragma unroll
            for (int i = 0; i < 4; i++) { ad[i] = dup2(aA.s[i]); ad[4 + i] = dup2(aB.s[i]); }
            #pragma unroll
            for (int i = 0; i < 8; i++) {
                ffma2(acc[i][0], ad[i], bA.u[0]);
                ffma2(acc[i][1], ad[i], bA.u[1]);
                ffma2(acc[i][2], ad[i], bB.u[0]);
                ffma2(acc[i][3], ad[i], bB.u[1]);
            }
        }
        __syncthreads();
    }

    #pragma unroll
    for (int i = 0; i < 8; i++) {
        int r = row0 + ty * 8 + i;
        int c = col0 + tx * 8;
        float o[8];
        unpk(acc[i][0], o[0], o[1]);
        unpk(acc[i][1], o[2], o[3]);
        unpk(acc[i][2], o[4], o[5]);
        unpk(acc[i][3], o[6], o[7]);
        float4 v0, v1;
        v0.x = o[0] + g_bias[c + 0]; v0.y = o[1] + g_bias[c + 1];
        v0.z = o[2] + g_bias[c + 2]; v0.w = o[3] + g_bias[c + 3];
        v1.x = o[4] + g_bias[c + 4]; v1.y = o[5] + g_bias[c + 5];
        v1.z = o[6] + g_bias[c + 6]; v1.w = o[7] + g_bias[c + 7];
        *(float4*)(g_Gx + (size_t)r * NG + c)     = v0;
        *(float4*)(g_Gx + (size_t)r * NG + c + 4) = v1;
    }
}

// ---------------------------------------------------------------------------
// Phase 2: persistent kernel. Grid (32,4) = 128 CTAs, 128 threads each.
// CTA(cx,ry): cols [cx*64, cx*64+64) (= 16 hidden units * 4 gates),
//             rows [ry*32, ry*32+32).
// Wh slice (512x64 = 128KB) resident in smem; c in registers; h via d_out.
// Microtile: 4 rows x 4 cols per thread (tx=unit 0..15, ty=rowgrp 0..7).
// ---------------------------------------------------------------------------
#define HSTRIDE 516   // floats per Hs row (bank-skewing pad, 16B-aligned)
#define SMEM_PERSIST ((512 * 64 + 32 * HSTRIDE) * 4)

__global__ __launch_bounds__(128, 1) void lstm_persist(float* __restrict__ out,
                                                       int write_final)
{
    extern __shared__ float smem[];
    float* Ws = smem;              // [512][64]
    float* Hs = smem + 512 * 64;   // [32][HSTRIDE]

    const int tid      = threadIdx.x;
    const int tx       = tid & 15;
    const int ty       = tid >> 4;
    const int tx4      = tx << 2;
    const int col0     = blockIdx.x * 64;
    const int row_base = blockIdx.y * 32;
    const int j        = (col0 >> 2) + tx;
    const int r0       = row_base + ty * 4;

    // Preload Wh slice into smem (once).
    #pragma unroll
    for (int i = 0; i < 64; i++) {
        int idx = tid + i * 128;            // 0..8191 float4s
        int k   = idx >> 4;
        int c   = (idx & 15) << 2;
        *(float4*)&Ws[k * 64 + c] = *(const float4*)(g_Wh + (size_t)k * NG + col0 + c);
    }
    __syncthreads();

    float creg[4]  = {0.f, 0.f, 0.f, 0.f};
    float hlast[4] = {0.f, 0.f, 0.f, 0.f};

    for (int t = 0; t < T_STEPS; t++) {
        ull acc[4][2];
        #pragma unroll
        for (int i = 0; i < 4; i++) { acc[i][0] = 0ull; acc[i][1] = 0ull; }

        if (t > 0) {
            // Fill Hs with h_{t-1} rows [row_base, row_base+32).
            const float* hp = out + (size_t)(t - 1) * BH;
            int hr = tid >> 2;                 // 0..31
            int cb = tid & 3;
            #pragma unroll
            for (int i = 0; i < 32; i++) {
                int c4 = (cb + i * 4) << 2;    // float col 0..508
                *(float4*)&Hs[hr * HSTRIDE + c4] =
                    *(const float4*)(hp + (size_t)(row_base + hr) * HID + c4);
            }
            __syncthreads();

            const float* hs = &Hs[(ty * 4) * HSTRIDE];
            #pragma unroll 2
            for (int k = 0; k < HID; k += 4) {
                F4U a0, a1, a2, a3;
                a0.f = *(const float4*)(hs + k);
                a1.f = *(const float4*)(hs + HSTRIDE + k);
                a2.f = *(const float4*)(hs + 2 * HSTRIDE + k);
                a3.f = *(const float4*)(hs + 3 * HSTRIDE + k);
                #pragma unroll
                for (int kk = 0; kk < 4; kk++) {
                    F4U b;
                    b.f = *(const float4*)&Ws[(k + kk) * 64 + tx4];
                    ull d0 = dup2(a0.s[kk]);
                    ull d1 = dup2(a1.s[kk]);
                    ull d2 = dup2(a2.s[kk]);
                    ull d3 = dup2(a3.s[kk]);
                    ffma2(acc[0][0], d0, b.u[0]); ffma2(acc[0][1], d0, b.u[1]);
                    ffma2(acc[1][0], d1, b.u[0]); ffma2(acc[1][1], d1, b.u[1]);
                    ffma2(acc[2][0], d2, b.u[0]); ffma2(acc[2][1], d2, b.u[1]);
                    ffma2(acc[3][0], d3, b.u[0]); ffma2(acc[3][1], d3, b.u[1]);
                }
            }
        }

        // Fused LSTM epilogue: this thread owns hidden unit j, rows r0..r0+3.
        const float* gxp = g_Gx + ((size_t)t * BATCH + r0) * NG + col0 + tx4;
        float*       orow = out + (size_t)t * BH;
        #pragma unroll
        for (int i = 0; i < 4; i++) {
            float4 gx = *(const float4*)(gxp + (size_t)i * NG);
            float pf, pi, pg, po;
            unpk(acc[i][0], pf, pi);
            unpk(acc[i][1], pg, po);
            float f  = sigm(pf + gx.x);
            float ii = sigm(pi + gx.y);
            float g  = tanh_(pg + gx.z);
            float o  = sigm(po + gx.w);
            float cn = f * creg[i] + ii * g;
            creg[i]  = cn;
            float h  = o * tanh_(cn);
            hlast[i] = h;
            orow[(size_t)(r0 + i) * HID + j] = h;
        }

        // Grid barrier (release h_t to all CTAs). Skip after the last step.
        if (t < T_STEPS - 1) {
            __syncthreads();
            if (tid == 0) {
                __threadfence();
                unsigned int old = atomicAdd(&g_bar_count, 1u);
                if (old == NCTA - 1) {
                    g_bar_count = 0;
                    __threadfence();
                    atomicAdd(&g_bar_gen, 1u);
                } else {
                    unsigned int target = (unsigned int)(t + 1);
                    while (*(volatile unsigned int*)&g_bar_gen < target)
                        __nanosleep(32);
                }
                __threadfence();
            }
            __syncthreads();
        }
    }

    if (write_final) {
        size_t base = (size_t)T_STEPS * BH;
        #pragma unroll
        for (int i = 0; i < 4; i++) {
            out[base + (size_t)(r0 + i) * HID + j]      = hlast[i];
            out[base + BH + (size_t)(r0 + i) * HID + j] = creg[i];
        }
    }
}

// ---------------------------------------------------------------------------
extern "C" void kernel_launch(void* const* d_in, const int* in_sizes, int n_in,
                              void* d_out, int out_size)
{
    const float* x  = (const float*)d_in[0];
    const float* Wf = (const float*)d_in[1];
    const float* bf = (const float*)d_in[2];
    const float* Wi = (const float*)d_in[3];
    const float* bi = (const float*)d_in[4];
    const float* Wg = (const float*)d_in[5];
    const float* bg = (const float*)d_in[6];
    const float* Wo = (const float*)d_in[7];
    const float* bo = (const float*)d_in[8];
    float* out = (float*)d_out;

    static int attr_set = 0;
    if (!attr_set) {
        cudaFuncSetAttribute(lstm_persist,
                             cudaFuncAttributeMaxDynamicSharedMemorySize,
                             SMEM_PERSIST);
        attr_set = 1;
    }

    prep_kernel<<<(DIN * NG + 255) / 256, 256>>>(Wf, bf, Wi, bi, Wg, bg, Wo, bo);

    dim3 g1(NG / BN, M_ALL / BM);
    sgemm_x<<<g1, 256>>>(x);

    long long need = (long long)T_STEPS * BH + 2LL * BH;
    int wf = ((long long)out_size >= need) ? 1 : 0;
    lstm_persist<<<dim3(32, 4), 128, SMEM_PERSIST>>>(out, wf);
}